// round 12
// baseline (speedup 1.0000x reference)
#include <cuda_runtime.h>
#include <cuda_fp16.h>
#include <cstdint>

// Problem constants (fixed by the dataset)
#define NN    50000
#define EE    1600000
#define RRC   32
#define BBC   8
#define DINC  128
#define DOUTC 128
#define KTOT  1152           // BBC*DINC + DINC (self-loop folded as 9th basis block)
#define MPAD  50048          // 128-row padded M so GEMM tiles load unguarded
#define BCAP  96             // per-node edge bucket capacity (max degree safety)

// ---------------- scratch (static __device__, no allocation) ----------------
// g_counts starts zero (static init) and every kernel_launch execution leaves
// it zero again (k_aggregate resets after reading) -> graph-replay determinism.
__device__ int   g_counts [NN + 1];
__device__ int   g_edges  [(size_t)NN * BCAP];   // bucketed: src | (etype << 20)
__device__ __align__(16) __half g_xh[(size_t)NN * DINC];    // fp16 copy of x (gather source)
__device__ __align__(16) __half g_ah[(size_t)MPAD * KTOT];  // A, fp16
__device__ __align__(16) __half g_bh[DOUTC * KTOT];         // B^T [128 n][1152 k], fp16

// ---------------- helpers ----------------
__device__ __forceinline__ uint32_t smem_u32(const void* p) {
    uint32_t a;
    asm("{ .reg .u64 t; cvta.to.shared.u64 t, %1; cvt.u32.u64 %0, t; }" : "=r"(a) : "l"(p));
    return a;
}
#define FFMA2(d, a, b) asm("fma.rn.f32x2 %0, %1, %2, %0;" : "+l"(d) : "l"(a), "l"(b))

__device__ __forceinline__ void ldsm4(uint32_t* r, uint32_t a) {
    asm volatile("ldmatrix.sync.aligned.m8n8.x4.shared.b16 {%0,%1,%2,%3}, [%4];"
        : "=r"(r[0]), "=r"(r[1]), "=r"(r[2]), "=r"(r[3]) : "r"(a));
}
__device__ __forceinline__ void mma16816(float* c, const uint32_t* a, uint32_t b0, uint32_t b1) {
    asm volatile("mma.sync.aligned.m16n8k16.row.col.f32.f16.f16.f32 "
        "{%0,%1,%2,%3},{%4,%5,%6,%7},{%8,%9},{%0,%1,%2,%3};"
        : "+f"(c[0]), "+f"(c[1]), "+f"(c[2]), "+f"(c[3])
        : "r"(a[0]), "r"(a[1]), "r"(a[2]), "r"(a[3]), "r"(b0), "r"(b1));
}
__device__ __forceinline__ void cpa16(uint32_t s, const void* g) {
    asm volatile("cp.async.cg.shared.global [%0], [%1], 16;" :: "r"(s), "l"(g));
}
#define CP_COMMIT() asm volatile("cp.async.commit_group;" ::: "memory")
#define CP_WAIT0()  asm volatile("cp.async.wait_group 0;"  ::: "memory")
#define CP_WAIT1()  asm volatile("cp.async.wait_group 1;"  ::: "memory")

// ---------------- merged front-end: pack B + convert x + bucket edges -------
__global__ void k_front(const float4* __restrict__ x4,
                        const float* __restrict__ w, const float* __restrict__ lw,
                        const int* __restrict__ src, const int* __restrict__ dst,
                        const int* __restrict__ et, int e, int n) {
    int i = blockIdx.x * blockDim.x + threadIdx.x;

    if (i < DOUTC * KTOT) {                        // pack B^T (fp16)
        int nn = i / KTOT;
        int k  = i % KTOT;
        float v;
        if (k < BBC * DINC) v = w[(size_t)k * DOUTC + nn];
        else                v = lw[(size_t)(k - BBC * DINC) * DOUTC + nn];
        g_bh[i] = __float2half_rn(v);
    }

    if (i < n * (DINC / 4)) {                      // x -> fp16 (1.6M float4)
        float4 f = x4[i];
        __half2 h0 = __floats2half2_rn(f.x, f.y);
        __half2 h1 = __floats2half2_rn(f.z, f.w);
        ((uint2*)g_xh)[i] = make_uint2(*(uint32_t*)&h0, *(uint32_t*)&h1);
    }

    int e4 = (e + 3) >> 2;                         // bucket 4 edges per thread
    if (i < e4) {
        int base = i * 4;
        if (base + 3 < e) {
            int4 d = *(const int4*)(dst + base);
            int4 s = *(const int4*)(src + base);
            int4 r = *(const int4*)(et  + base);
            int p0 = atomicAdd(&g_counts[d.x], 1);
            int p1 = atomicAdd(&g_counts[d.y], 1);
            int p2 = atomicAdd(&g_counts[d.z], 1);
            int p3 = atomicAdd(&g_counts[d.w], 1);
            if (p0 < BCAP) g_edges[(size_t)d.x * BCAP + p0] = s.x | (r.x << 20);
            if (p1 < BCAP) g_edges[(size_t)d.y * BCAP + p1] = s.y | (r.y << 20);
            if (p2 < BCAP) g_edges[(size_t)d.z * BCAP + p2] = s.z | (r.z << 20);
            if (p3 < BCAP) g_edges[(size_t)d.w * BCAP + p3] = s.w | (r.w << 20);
        } else {
            for (int j = base; j < e; ++j) {
                int p = atomicAdd(&g_counts[dst[j]], 1);
                if (p < BCAP) g_edges[(size_t)dst[j] * BCAP + p] = src[j] | (et[j] << 20);
            }
        }
    }
}

// ---------------- aggregation (warp/node, fp16 gather + fp16 A out) ---------
__global__ void __launch_bounds__(256) k_aggregate(const float* __restrict__ wcomp,
                                                   int n) {
    __shared__ unsigned long long cwp[RRC][BBC];   // pre-duplicated f32x2 coefficients
    int t = threadIdx.x;
    {
        float c = wcomp[t];
        unsigned long long d;
        asm("mov.b64 %0, {%1, %1};" : "=l"(d) : "f"(c));
        cwp[t >> 3][t & 7] = d;
    }
    __syncthreads();

    int warp = t >> 5, lane = t & 31;
    int node = blockIdx.x * 8 + warp;
    if (node >= MPAD) return;

    uint2* arow = (uint2*)(g_ah + (size_t)node * KTOT);  // lane -> dims [4l,4l+4)

    if (node >= n) {                                // zero padding rows
        uint2 z = make_uint2(0u, 0u);
        #pragma unroll
        for (int b = 0; b < 9; ++b) arow[b * 32 + lane] = z;
        return;
    }

    const uint2* xh = ((const uint2*)g_xh) + lane;

    unsigned long long a[8][2];
    #pragma unroll
    for (int b = 0; b < 8; ++b) { a[b][0] = 0ULL; a[b][1] = 0ULL; }

    const int* eb = g_edges + (size_t)node * BCAP;
    int cnt = min(g_counts[node], BCAP);
    if (lane == 0) g_counts[node] = 0;              // leave clean for next replay

    int e = 0;
    for (; e + 7 < cnt; e += 8) {
        int p[8];
        uint2 hv[8];
        #pragma unroll
        for (int j = 0; j < 8; ++j) p[j] = eb[e + j];
        #pragma unroll
        for (int j = 0; j < 8; ++j) hv[j] = __ldcg(&xh[(size_t)(p[j] & 0xFFFFF) * 32]);
        #pragma unroll
        for (int j = 0; j < 8; ++j) {
            float2 f01 = __half22float2(*(__half2*)&hv[j].x);
            float2 f23 = __half22float2(*(__half2*)&hv[j].y);
            unsigned long long q0, q1;
            asm("mov.b64 %0, {%1, %2};" : "=l"(q0) : "f"(f01.x), "f"(f01.y));
            asm("mov.b64 %0, {%1, %2};" : "=l"(q1) : "f"(f23.x), "f"(f23.y));
            const ulonglong2* cc = (const ulonglong2*)cwp[p[j] >> 20];
            #pragma unroll
            for (int q = 0; q < 4; ++q) {
                ulonglong2 cp = cc[q];
                FFMA2(a[2*q  ][0], q0, cp.x);
                FFMA2(a[2*q  ][1], q1, cp.x);
                FFMA2(a[2*q+1][0], q0, cp.y);
                FFMA2(a[2*q+1][1], q1, cp.y);
            }
        }
    }
    for (; e < cnt; ++e) {
        int p0 = eb[e];
        uint2 hv0 = __ldcg(&xh[(size_t)(p0 & 0xFFFFF) * 32]);
        float2 f01 = __half22float2(*(__half2*)&hv0.x);
        float2 f23 = __half22float2(*(__half2*)&hv0.y);
        unsigned long long q0, q1;
        asm("mov.b64 %0, {%1, %2};" : "=l"(q0) : "f"(f01.x), "f"(f01.y));
        asm("mov.b64 %0, {%1, %2};" : "=l"(q1) : "f"(f23.x), "f"(f23.y));
        const ulonglong2* cc = (const ulonglong2*)cwp[p0 >> 20];
        #pragma unroll
        for (int q = 0; q < 4; ++q) {
            ulonglong2 cp = cc[q];
            FFMA2(a[2*q  ][0], q0, cp.x);
            FFMA2(a[2*q  ][1], q1, cp.x);
            FFMA2(a[2*q+1][0], q0, cp.y);
            FFMA2(a[2*q+1][1], q1, cp.y);
        }
    }

    #pragma unroll
    for (int b = 0; b < 8; ++b) {
        float f0, f1, f2, f3;
        asm("mov.b64 {%0, %1}, %2;" : "=f"(f0), "=f"(f1) : "l"(a[b][0]));
        asm("mov.b64 {%0, %1}, %2;" : "=f"(f2), "=f"(f3) : "l"(a[b][1]));
        __half2 h0 = __floats2half2_rn(f0, f1);
        __half2 h1 = __floats2half2_rn(f2, f3);
        arow[b * 32 + lane] = make_uint2(*(uint32_t*)&h0, *(uint32_t*)&h1);
    }
    // self-loop block (b = 8): fp16 mirror row
    arow[8 * 32 + lane] = xh[(size_t)node * 32];
}

// ---------------- fp16 mma.sync GEMM: out = relu(A @ B^T + bias) -------------
// CTA: 128(M) x 128(N), 256 threads = 8 warps (4M x 2N), warp tile 32x64.
// K in 18 chunks of 64 fp16, cp.async TRIPLE buffered, register
// double-buffered fragments (prefetch next ldsm while mma chain runs).
#define KC      64
#define NCH     18
#define ROWB    144
#define OFF_A   0u
#define OFF_B   18432u
#define STG     36864u
#define GEMM_SMEM (3 * STG)

__global__ void __launch_bounds__(256, 2) k_gemm_mma(const float* __restrict__ bias,
                                                     float* __restrict__ out, int n) {
    extern __shared__ char sm[];
    __shared__ float s_bias[128];
    uint32_t sbase = smem_u32(sm);

    int tid  = threadIdx.x;
    int lane = tid & 31;
    int w    = tid >> 5;
    int mw   = w >> 1;                 // 0..3
    int nw   = w & 1;                  // 0..1
    if (tid < 128) s_bias[tid] = bias[tid];

    int m0 = blockIdx.x * 128;

    // cp.async mapping: row = tid>>1 (0..127), 4 x 16B chunks per thread
    int l_row = tid >> 1;
    int l_c0  = (tid & 1) * 4;

    // ldmatrix lane address components
    uint32_t a_lm = (uint32_t)((lane & 15) * ROWB + ((lane >> 4) << 4));
    uint32_t b_lm = (uint32_t)((((lane & 7) + ((lane >> 4) << 3)) * ROWB) + (((lane >> 3) & 1) << 4));

    float acc[2][8][4];
    #pragma unroll
    for (int i = 0; i < 2; ++i)
        #pragma unroll
        for (int nt = 0; nt < 8; ++nt)
            #pragma unroll
            for (int q = 0; q < 4; ++q) acc[i][nt][q] = 0.f;

    #define LOAD_STAGE(cidx, s) do {                                                  \
        size_t kc = (size_t)(cidx) * KC;                                              \
        uint32_t sb = sbase + (uint32_t)(s) * STG;                                     \
        _Pragma("unroll")                                                              \
        for (int j = 0; j < 4; ++j) {                                                  \
            int cc = l_c0 + j;                                                         \
            uint32_t so = (uint32_t)(l_row * ROWB + cc * 16);                          \
            cpa16(sb + OFF_A + so,                                                     \
                  (const char*)(g_ah + (size_t)(m0 + l_row) * KTOT + kc) + cc * 16);   \
            cpa16(sb + OFF_B + so,                                                     \
                  (const char*)(g_bh + (size_t)l_row * KTOT + kc) + cc * 16);          \
        }                                                                              \
        CP_COMMIT();                                                                   \
    } while (0)

    LOAD_STAGE(0, 0);
    LOAD_STAGE(1, 1);
    CP_WAIT1();
    __syncthreads();

    int stg = 0;
    for (int c = 0; c < NCH; ++c) {
        if (c + 2 < NCH) {
            int ns = stg + 2; if (ns >= 3) ns -= 3;
            LOAD_STAGE(c + 2, ns);
        }

        uint32_t sb   = sbase + (uint32_t)stg * STG;
        uint32_t aoff = sb + OFF_A + (uint32_t)((mw * 32) * ROWB) + a_lm;
        uint32_t boff = sb + OFF_B + (uint32_t)((nw * 64) * ROWB) + b_lm;

        uint32_t Ab[2][2][4];            // [ks parity][i tile][frag]
        uint32_t Bb[2][4];               // [step parity][frag]
        ldsm4(Ab[0][0], aoff);
        ldsm4(Ab[0][1], aoff + 16 * ROWB);
        ldsm4(Bb[0],    boff);

        #pragma unroll
        for (int step = 0; step < 16; ++step) {
            const int ks = step >> 2, jp = step & 3;
            const int ap = ks & 1, bp = step & 1;
            // prefetch next ks A tiles early in each ks
            if (jp == 0 && ks < 3) {
                ldsm4(Ab[ap ^ 1][0], aoff + (uint32_t)((ks + 1) * 32));
                ldsm4(Ab[ap ^ 1][1], aoff + (uint32_t)(16 * ROWB + (ks + 1) * 32));
            }
            // prefetch next B fragment
            if (step < 15) {
                const int s2 = step + 1, ks2 = s2 >> 2, jp2 = s2 & 3;
                ldsm4(Bb[bp ^ 1], boff + (uint32_t)(jp2 * 16 * ROWB + ks2 * 32));
            }
            mma16816(acc[0][2*jp  ], Ab[ap][0], Bb[bp][0], Bb[bp][1]);
            mma16816(acc[0][2*jp+1], Ab[ap][0], Bb[bp][2], Bb[bp][3]);
            mma16816(acc[1][2*jp  ], Ab[ap][1], Bb[bp][0], Bb[bp][1]);
            mma16816(acc[1][2*jp+1], Ab[ap][1], Bb[bp][2], Bb[bp][3]);
        }

        if (c + 1 < NCH) {
            if (c + 2 < NCH) { CP_WAIT1(); } else { CP_WAIT0(); }
            __syncthreads();
        }
        if (++stg >= 3) stg = 0;
    }

    // ---- epilogue: bias + relu ----
    #pragma unroll
    for (int i = 0; i < 2; ++i) {
        int mbase = m0 + mw * 32 + i * 16 + (lane >> 2);
        #pragma unroll
        for (int nt = 0; nt < 8; ++nt) {
            int col = nw * 64 + nt * 8 + 2 * (lane & 3);
            float b0 = s_bias[col], b1 = s_bias[col + 1];
            float* cfr = acc[i][nt];
            if (mbase < n) {
                float2 v = make_float2(fmaxf(cfr[0] + b0, 0.f), fmaxf(cfr[1] + b1, 0.f));
                *(float2*)(out + (size_t)mbase * DOUTC + col) = v;
            }
            if (mbase + 8 < n) {
                float2 v = make_float2(fmaxf(cfr[2] + b0, 0.f), fmaxf(cfr[3] + b1, 0.f));
                *(float2*)(out + (size_t)(mbase + 8) * DOUTC + col) = v;
            }
        }
    }
}

// ---------------- launch ----------------
extern "C" void kernel_launch(void* const* d_in, const int* in_sizes, int n_in,
                              void* d_out, int out_size) {
    const float* x      = (const float*)d_in[0];
    const int*   src    = (const int*)  d_in[1];
    const int*   dst    = (const int*)  d_in[2];
    const int*   etypes = (const int*)  d_in[3];
    const float* weight = (const float*)d_in[4];
    const float* w_comp = (const float*)d_in[5];
    const float* h_bias = (const float*)d_in[6];
    const float* loop_w = (const float*)d_in[7];
    float* out = (float*)d_out;

    int n = in_sizes[0] / DINC;   // 50000
    int e = in_sizes[1];          // 1600000

    static int attr_set = 0;
    if (!attr_set) {
        cudaFuncSetAttribute(k_gemm_mma, cudaFuncAttributeMaxDynamicSharedMemorySize, GEMM_SMEM);
        attr_set = 1;
    }

    int nfront = n * (DINC / 4);  // 1.6M threads covers all front-end work
    k_front <<<(nfront + 255) / 256, 256>>>((const float4*)x, weight, loop_w,
                                            src, dst, etypes, e, n);
    k_aggregate<<<MPAD / 8, 256>>>(w_comp, n);
    k_gemm_mma<<<MPAD / 128, 256, GEMM_SMEM>>>(h_bias, out, n);
}

// round 13
// speedup vs baseline: 1.0164x; 1.0164x over previous
#include <cuda_runtime.h>
#include <cuda_fp16.h>
#include <cstdint>

// Problem constants (fixed by the dataset)
#define NN    50000
#define EE    1600000
#define RRC   32
#define BBC   8
#define DINC  128
#define DOUTC 128
#define KTOT  1152           // BBC*DINC + DINC (self-loop folded as 9th basis block)
#define MPAD  50048          // 128-row padded M so GEMM tiles load unguarded
#define BCAP  96             // per-node edge bucket capacity (max degree safety)

// ---------------- scratch (static __device__, no allocation) ----------------
// g_counts starts zero (static init) and every kernel_launch execution leaves
// it zero again (k_aggregate resets after reading) -> graph-replay determinism.
__device__ int   g_counts [NN + 1];
__device__ int   g_edges  [(size_t)NN * BCAP];   // bucketed: src | (etype << 20)
__device__ __align__(16) __half g_xh[(size_t)NN * DINC];    // fp16 copy of x (gather source)
__device__ __align__(16) __half g_ah[(size_t)MPAD * KTOT];  // A, fp16
__device__ __align__(16) __half g_bh[DOUTC * KTOT];         // B^T [128 n][1152 k], fp16

// ---------------- helpers ----------------
__device__ __forceinline__ uint32_t smem_u32(const void* p) {
    uint32_t a;
    asm("{ .reg .u64 t; cvta.to.shared.u64 t, %1; cvt.u32.u64 %0, t; }" : "=r"(a) : "l"(p));
    return a;
}
#define FFMA2(d, a, b) asm("fma.rn.f32x2 %0, %1, %2, %0;" : "+l"(d) : "l"(a), "l"(b))

__device__ __forceinline__ void ldsm4(uint32_t* r, uint32_t a) {
    asm volatile("ldmatrix.sync.aligned.m8n8.x4.shared.b16 {%0,%1,%2,%3}, [%4];"
        : "=r"(r[0]), "=r"(r[1]), "=r"(r[2]), "=r"(r[3]) : "r"(a));
}
__device__ __forceinline__ void mma16816(float* c, const uint32_t* a, uint32_t b0, uint32_t b1) {
    asm volatile("mma.sync.aligned.m16n8k16.row.col.f32.f16.f16.f32 "
        "{%0,%1,%2,%3},{%4,%5,%6,%7},{%8,%9},{%0,%1,%2,%3};"
        : "+f"(c[0]), "+f"(c[1]), "+f"(c[2]), "+f"(c[3])
        : "r"(a[0]), "r"(a[1]), "r"(a[2]), "r"(a[3]), "r"(b0), "r"(b1));
}
__device__ __forceinline__ void cpa16(uint32_t s, const void* g) {
    asm volatile("cp.async.cg.shared.global [%0], [%1], 16;" :: "r"(s), "l"(g));
}
#define CP_COMMIT() asm volatile("cp.async.commit_group;" ::: "memory")
#define CP_WAIT0()  asm volatile("cp.async.wait_group 0;"  ::: "memory")
#define CP_WAIT1()  asm volatile("cp.async.wait_group 1;"  ::: "memory")

// ---------------- merged front-end: pack B + convert x + bucket edges -------
__global__ void k_front(const float4* __restrict__ x4,
                        const float* __restrict__ w, const float* __restrict__ lw,
                        const int* __restrict__ src, const int* __restrict__ dst,
                        const int* __restrict__ et, int e, int n) {
    int i = blockIdx.x * blockDim.x + threadIdx.x;

    if (i < DOUTC * KTOT) {                        // pack B^T (fp16)
        int nn = i / KTOT;
        int k  = i % KTOT;
        float v;
        if (k < BBC * DINC) v = w[(size_t)k * DOUTC + nn];
        else                v = lw[(size_t)(k - BBC * DINC) * DOUTC + nn];
        g_bh[i] = __float2half_rn(v);
    }

    if (i < n * (DINC / 4)) {                      // x -> fp16 (1.6M float4)
        float4 f = x4[i];
        __half2 h0 = __floats2half2_rn(f.x, f.y);
        __half2 h1 = __floats2half2_rn(f.z, f.w);
        ((uint2*)g_xh)[i] = make_uint2(*(uint32_t*)&h0, *(uint32_t*)&h1);
    }

    int e4 = (e + 3) >> 2;                         // bucket 4 edges per thread
    if (i < e4) {
        int base = i * 4;
        if (base + 3 < e) {
            int4 d = *(const int4*)(dst + base);
            int4 s = *(const int4*)(src + base);
            int4 r = *(const int4*)(et  + base);
            int p0 = atomicAdd(&g_counts[d.x], 1);
            int p1 = atomicAdd(&g_counts[d.y], 1);
            int p2 = atomicAdd(&g_counts[d.z], 1);
            int p3 = atomicAdd(&g_counts[d.w], 1);
            if (p0 < BCAP) g_edges[(size_t)d.x * BCAP + p0] = s.x | (r.x << 20);
            if (p1 < BCAP) g_edges[(size_t)d.y * BCAP + p1] = s.y | (r.y << 20);
            if (p2 < BCAP) g_edges[(size_t)d.z * BCAP + p2] = s.z | (r.z << 20);
            if (p3 < BCAP) g_edges[(size_t)d.w * BCAP + p3] = s.w | (r.w << 20);
        } else {
            for (int j = base; j < e; ++j) {
                int p = atomicAdd(&g_counts[dst[j]], 1);
                if (p < BCAP) g_edges[(size_t)dst[j] * BCAP + p] = src[j] | (et[j] << 20);
            }
        }
    }
}

// ---------------- aggregation (warp/node, fp16 gather + fp16 A out) ---------
__global__ void __launch_bounds__(256) k_aggregate(const float* __restrict__ wcomp,
                                                   int n) {
    __shared__ unsigned long long cwp[RRC][BBC];   // pre-duplicated f32x2 coefficients
    int t = threadIdx.x;
    {
        float c = wcomp[t];
        unsigned long long d;
        asm("mov.b64 %0, {%1, %1};" : "=l"(d) : "f"(c));
        cwp[t >> 3][t & 7] = d;
    }
    __syncthreads();

    int warp = t >> 5, lane = t & 31;
    int node = blockIdx.x * 8 + warp;
    if (node >= MPAD) return;

    uint2* arow = (uint2*)(g_ah + (size_t)node * KTOT);  // lane -> dims [4l,4l+4)

    if (node >= n) {                                // zero padding rows
        uint2 z = make_uint2(0u, 0u);
        #pragma unroll
        for (int b = 0; b < 9; ++b) arow[b * 32 + lane] = z;
        return;
    }

    const uint2* xh = ((const uint2*)g_xh) + lane;

    unsigned long long a[8][2];
    #pragma unroll
    for (int b = 0; b < 8; ++b) { a[b][0] = 0ULL; a[b][1] = 0ULL; }

    const int* eb = g_edges + (size_t)node * BCAP;
    int cnt = min(g_counts[node], BCAP);
    if (lane == 0) g_counts[node] = 0;              // leave clean for next replay

    int e = 0;
    for (; e + 7 < cnt; e += 8) {
        int p[8];
        uint2 hv[8];
        #pragma unroll
        for (int j = 0; j < 8; ++j) p[j] = eb[e + j];
        #pragma unroll
        for (int j = 0; j < 8; ++j) hv[j] = __ldcg(&xh[(size_t)(p[j] & 0xFFFFF) * 32]);
        #pragma unroll
        for (int j = 0; j < 8; ++j) {
            float2 f01 = __half22float2(*(__half2*)&hv[j].x);
            float2 f23 = __half22float2(*(__half2*)&hv[j].y);
            unsigned long long q0, q1;
            asm("mov.b64 %0, {%1, %2};" : "=l"(q0) : "f"(f01.x), "f"(f01.y));
            asm("mov.b64 %0, {%1, %2};" : "=l"(q1) : "f"(f23.x), "f"(f23.y));
            const ulonglong2* cc = (const ulonglong2*)cwp[p[j] >> 20];
            #pragma unroll
            for (int q = 0; q < 4; ++q) {
                ulonglong2 cp = cc[q];
                FFMA2(a[2*q  ][0], q0, cp.x);
                FFMA2(a[2*q  ][1], q1, cp.x);
                FFMA2(a[2*q+1][0], q0, cp.y);
                FFMA2(a[2*q+1][1], q1, cp.y);
            }
        }
    }
    for (; e < cnt; ++e) {
        int p0 = eb[e];
        uint2 hv0 = __ldcg(&xh[(size_t)(p0 & 0xFFFFF) * 32]);
        float2 f01 = __half22float2(*(__half2*)&hv0.x);
        float2 f23 = __half22float2(*(__half2*)&hv0.y);
        unsigned long long q0, q1;
        asm("mov.b64 %0, {%1, %2};" : "=l"(q0) : "f"(f01.x), "f"(f01.y));
        asm("mov.b64 %0, {%1, %2};" : "=l"(q1) : "f"(f23.x), "f"(f23.y));
        const ulonglong2* cc = (const ulonglong2*)cwp[p0 >> 20];
        #pragma unroll
        for (int q = 0; q < 4; ++q) {
            ulonglong2 cp = cc[q];
            FFMA2(a[2*q  ][0], q0, cp.x);
            FFMA2(a[2*q  ][1], q1, cp.x);
            FFMA2(a[2*q+1][0], q0, cp.y);
            FFMA2(a[2*q+1][1], q1, cp.y);
        }
    }

    #pragma unroll
    for (int b = 0; b < 8; ++b) {
        float f0, f1, f2, f3;
        asm("mov.b64 {%0, %1}, %2;" : "=f"(f0), "=f"(f1) : "l"(a[b][0]));
        asm("mov.b64 {%0, %1}, %2;" : "=f"(f2), "=f"(f3) : "l"(a[b][1]));
        __half2 h0 = __floats2half2_rn(f0, f1);
        __half2 h1 = __floats2half2_rn(f2, f3);
        arow[b * 32 + lane] = make_uint2(*(uint32_t*)&h0, *(uint32_t*)&h1);
    }
    // self-loop block (b = 8): fp16 mirror row
    arow[8 * 32 + lane] = xh[(size_t)node * 32];
}

// ---------------- fp16 mma.sync GEMM: out = relu(A @ B^T + bias) -------------
// CTA: 128(M) x 128(N), 256 threads = 8 warps (4M x 2N), warp tile 32x64.
// K streamed in 18 chunks of 64 fp16, cp.async TRIPLE buffered.
// Row stride = 144B (128B data + 16 pad) -> conflict-free ldmatrix.
// (R10-proven mainloop: 78.4us, 96 regs -- do not hand-schedule.)
#define KC      64
#define NCH     18
#define ROWB    144
#define OFF_A   0u
#define OFF_B   18432u
#define STG     36864u
#define GEMM_SMEM (3 * STG)

__global__ void __launch_bounds__(256) k_gemm_mma(const float* __restrict__ bias,
                                                  float* __restrict__ out, int n) {
    extern __shared__ char sm[];
    __shared__ float s_bias[128];
    uint32_t sbase = smem_u32(sm);

    int tid  = threadIdx.x;
    int lane = tid & 31;
    int w    = tid >> 5;
    int mw   = w >> 1;                 // 0..3
    int nw   = w & 1;                  // 0..1
    if (tid < 128) s_bias[tid] = bias[tid];

    int m0 = blockIdx.x * 128;

    // cp.async mapping: row = tid>>1 (0..127), 4 x 16B chunks per thread
    int l_row = tid >> 1;
    int l_c0  = (tid & 1) * 4;

    // ldmatrix lane address components (b16 K-major)
    uint32_t a_lm = (uint32_t)((lane & 15) * ROWB + ((lane >> 4) << 4));
    uint32_t b_lm = (uint32_t)((((lane & 7) + ((lane >> 4) << 3)) * ROWB) + (((lane >> 3) & 1) << 4));

    float acc[2][8][4];
    #pragma unroll
    for (int i = 0; i < 2; ++i)
        #pragma unroll
        for (int nt = 0; nt < 8; ++nt)
            #pragma unroll
            for (int q = 0; q < 4; ++q) acc[i][nt][q] = 0.f;

    #define LOAD_STAGE(cidx, s) do {                                                  \
        size_t kc = (size_t)(cidx) * KC;                                              \
        uint32_t sb = sbase + (uint32_t)(s) * STG;                                     \
        _Pragma("unroll")                                                              \
        for (int j = 0; j < 4; ++j) {                                                  \
            int cc = l_c0 + j;                                                         \
            uint32_t so = (uint32_t)(l_row * ROWB + cc * 16);                          \
            cpa16(sb + OFF_A + so,                                                     \
                  (const char*)(g_ah + (size_t)(m0 + l_row) * KTOT + kc) + cc * 16);   \
            cpa16(sb + OFF_B + so,                                                     \
                  (const char*)(g_bh + (size_t)l_row * KTOT + kc) + cc * 16);          \
        }                                                                              \
        CP_COMMIT();                                                                   \
    } while (0)

    LOAD_STAGE(0, 0);
    LOAD_STAGE(1, 1);
    CP_WAIT1();
    __syncthreads();

    int stg = 0;
    for (int c = 0; c < NCH; ++c) {
        if (c + 2 < NCH) {
            int ns = stg + 2; if (ns >= 3) ns -= 3;
            LOAD_STAGE(c + 2, ns);
        }

        uint32_t sb = sbase + (uint32_t)stg * STG;
        #pragma unroll
        for (int ks = 0; ks < 4; ++ks) {           // 4 x k16 slices (32B each)
            uint32_t kb = ks * 32;
            uint32_t A[2][4];
            #pragma unroll
            for (int i = 0; i < 2; ++i)
                ldsm4(A[i], sb + OFF_A + (uint32_t)((mw * 32 + i * 16) * ROWB) + a_lm + kb);
            #pragma unroll
            for (int jp = 0; jp < 4; ++jp) {
                uint32_t B[4];
                ldsm4(B, sb + OFF_B + (uint32_t)((nw * 64 + jp * 16) * ROWB) + b_lm + kb);
                #pragma unroll
                for (int i = 0; i < 2; ++i) {
                    mma16816(acc[i][2*jp  ], A[i], B[0], B[1]);
                    mma16816(acc[i][2*jp+1], A[i], B[2], B[3]);
                }
            }
        }

        if (c + 1 < NCH) {
            if (c + 2 < NCH) { CP_WAIT1(); } else { CP_WAIT0(); }
            __syncthreads();
        }
        if (++stg >= 3) stg = 0;
    }

    // ---- epilogue: bias + relu ----
    #pragma unroll
    for (int i = 0; i < 2; ++i) {
        int mbase = m0 + mw * 32 + i * 16 + (lane >> 2);
        #pragma unroll
        for (int nt = 0; nt < 8; ++nt) {
            int col = nw * 64 + nt * 8 + 2 * (lane & 3);
            float b0 = s_bias[col], b1 = s_bias[col + 1];
            float* cfr = acc[i][nt];
            if (mbase < n) {
                float2 v = make_float2(fmaxf(cfr[0] + b0, 0.f), fmaxf(cfr[1] + b1, 0.f));
                *(float2*)(out + (size_t)mbase * DOUTC + col) = v;
            }
            if (mbase + 8 < n) {
                float2 v = make_float2(fmaxf(cfr[2] + b0, 0.f), fmaxf(cfr[3] + b1, 0.f));
                *(float2*)(out + (size_t)(mbase + 8) * DOUTC + col) = v;
            }
        }
    }
}

// ---------------- launch ----------------
extern "C" void kernel_launch(void* const* d_in, const int* in_sizes, int n_in,
                              void* d_out, int out_size) {
    const float* x      = (const float*)d_in[0];
    const int*   src    = (const int*)  d_in[1];
    const int*   dst    = (const int*)  d_in[2];
    const int*   etypes = (const int*)  d_in[3];
    const float* weight = (const float*)d_in[4];
    const float* w_comp = (const float*)d_in[5];
    const float* h_bias = (const float*)d_in[6];
    const float* loop_w = (const float*)d_in[7];
    float* out = (float*)d_out;

    int n = in_sizes[0] / DINC;   // 50000
    int e = in_sizes[1];          // 1600000

    static int attr_set = 0;
    if (!attr_set) {
        cudaFuncSetAttribute(k_gemm_mma, cudaFuncAttributeMaxDynamicSharedMemorySize, GEMM_SMEM);
        attr_set = 1;
    }

    int nfront = n * (DINC / 4);  // 1.6M threads covers all front-end work
    k_front <<<(nfront + 255) / 256, 256>>>((const float4*)x, weight, loop_w,
                                            src, dst, etypes, e, n);
    k_aggregate<<<MPAD / 8, 256>>>(w_comp, n);
    k_gemm_mma<<<MPAD / 128, 256, GEMM_SMEM>>>(h_bias, out, n);
}

// round 14
// speedup vs baseline: 1.2677x; 1.2473x over previous
#include <cuda_runtime.h>
#include <cuda_fp16.h>
#include <cstdint>

// Problem constants (fixed by the dataset)
#define NN    50000
#define EE    1600000
#define RRC   32
#define BBC   8
#define DINC  128
#define DOUTC 128
#define KTOT  1152           // BBC*DINC + DINC (self-loop folded as 9th basis block)
#define MPAD  50048          // 128-row padded M so GEMM tiles load unguarded
#define BCAP  96             // per-node edge bucket capacity (max degree safety)

// ---------------- scratch (static __device__, no allocation) ----------------
__device__ int   g_counts [NN + 1];
__device__ int   g_edges  [(size_t)NN * BCAP];   // bucketed: src | (etype << 20)
__device__ __align__(16) __half g_xh[(size_t)NN * DINC];    // fp16 copy of x (gather source)
__device__ __align__(16) __half g_ah[(size_t)MPAD * KTOT];  // A, fp16
__device__ __align__(16) __half g_bh[DOUTC * KTOT];         // B^T [128 n][1152 k], fp16

// ---------------- helpers ----------------
__device__ __forceinline__ uint32_t smem_u32(const void* p) {
    uint32_t a;
    asm("{ .reg .u64 t; cvta.to.shared.u64 t, %1; cvt.u32.u64 %0, t; }" : "=r"(a) : "l"(p));
    return a;
}
#define FFMA2(d, a, b) asm("fma.rn.f32x2 %0, %1, %2, %0;" : "+l"(d) : "l"(a), "l"(b))

__device__ __forceinline__ void ldsm4(uint32_t* r, uint32_t a) {
    asm volatile("ldmatrix.sync.aligned.m8n8.x4.shared.b16 {%0,%1,%2,%3}, [%4];"
        : "=r"(r[0]), "=r"(r[1]), "=r"(r[2]), "=r"(r[3]) : "r"(a));
}
__device__ __forceinline__ void mma16816(float* c, const uint32_t* a, uint32_t b0, uint32_t b1) {
    asm volatile("mma.sync.aligned.m16n8k16.row.col.f32.f16.f16.f32 "
        "{%0,%1,%2,%3},{%4,%5,%6,%7},{%8,%9},{%0,%1,%2,%3};"
        : "+f"(c[0]), "+f"(c[1]), "+f"(c[2]), "+f"(c[3])
        : "r"(a[0]), "r"(a[1]), "r"(a[2]), "r"(a[3]), "r"(b0), "r"(b1));
}
__device__ __forceinline__ void cpa16(uint32_t s, const void* g) {
    asm volatile("cp.async.cg.shared.global [%0], [%1], 16;" :: "r"(s), "l"(g));
}
#define CP_COMMIT() asm volatile("cp.async.commit_group;" ::: "memory")
#define CP_WAIT0()  asm volatile("cp.async.wait_group 0;"  ::: "memory")
#define CP_WAIT1()  asm volatile("cp.async.wait_group 1;"  ::: "memory")

// ---------------- front-end kernels ----------------
__global__ void k_zero(int n) {
    int i = blockIdx.x * blockDim.x + threadIdx.x;
    if (i <= n) g_counts[i] = 0;
}

// merged: pack B^T (fp16) + convert x -> fp16 + bucket edges (atomic rank)
__global__ void k_front(const float4* __restrict__ x4,
                        const float* __restrict__ w, const float* __restrict__ lw,
                        const int* __restrict__ src, const int* __restrict__ dst,
                        const int* __restrict__ et, int e, int n) {
    int i = blockIdx.x * blockDim.x + threadIdx.x;

    if (i < DOUTC * KTOT) {                        // pack B^T (fp16)
        int nn = i / KTOT;
        int k  = i % KTOT;
        float v;
        if (k < BBC * DINC) v = w[(size_t)k * DOUTC + nn];
        else                v = lw[(size_t)(k - BBC * DINC) * DOUTC + nn];
        g_bh[i] = __float2half_rn(v);
    }

    if (i < n * (DINC / 4)) {                      // x -> fp16 (1.6M float4)
        float4 f = x4[i];
        __half2 h0 = __floats2half2_rn(f.x, f.y);
        __half2 h1 = __floats2half2_rn(f.z, f.w);
        ((uint2*)g_xh)[i] = make_uint2(*(uint32_t*)&h0, *(uint32_t*)&h1);
    }

    int e4 = (e + 3) >> 2;                         // bucket 4 edges per thread
    if (i < e4) {
        int base = i * 4;
        if (base + 3 < e) {
            int4 d = *(const int4*)(dst + base);
            int4 s = *(const int4*)(src + base);
            int4 r = *(const int4*)(et  + base);
            int p0 = atomicAdd(&g_counts[d.x], 1);
            int p1 = atomicAdd(&g_counts[d.y], 1);
            int p2 = atomicAdd(&g_counts[d.z], 1);
            int p3 = atomicAdd(&g_counts[d.w], 1);
            if (p0 < BCAP) g_edges[(size_t)d.x * BCAP + p0] = s.x | (r.x << 20);
            if (p1 < BCAP) g_edges[(size_t)d.y * BCAP + p1] = s.y | (r.y << 20);
            if (p2 < BCAP) g_edges[(size_t)d.z * BCAP + p2] = s.z | (r.z << 20);
            if (p3 < BCAP) g_edges[(size_t)d.w * BCAP + p3] = s.w | (r.w << 20);
        } else {
            for (int j = base; j < e; ++j) {
                int p = atomicAdd(&g_counts[dst[j]], 1);
                if (p < BCAP) g_edges[(size_t)dst[j] * BCAP + p] = src[j] | (et[j] << 20);
            }
        }
    }
}

// ---------------- aggregation (EXACT R10: warp/node, fp16 gather, no reset) -
__global__ void __launch_bounds__(256) k_aggregate(const float4* __restrict__ x4,
                                                   const float*  __restrict__ wcomp,
                                                   int n) {
    __shared__ unsigned long long cwp[RRC][BBC];   // pre-duplicated f32x2 coefficients
    int t = threadIdx.x;
    {
        float c = wcomp[t];
        unsigned long long d;
        asm("mov.b64 %0, {%1, %1};" : "=l"(d) : "f"(c));
        cwp[t >> 3][t & 7] = d;
    }
    __syncthreads();

    int warp = t >> 5, lane = t & 31;
    int node = blockIdx.x * 8 + warp;
    if (node >= MPAD) return;

    uint2* arow = (uint2*)(g_ah + (size_t)node * KTOT);  // lane -> dims [4l,4l+4)

    if (node >= n) {                                // zero padding rows
        uint2 z = make_uint2(0u, 0u);
        #pragma unroll
        for (int b = 0; b < 9; ++b) arow[b * 32 + lane] = z;
        return;
    }

    const uint2* xh = ((const uint2*)g_xh) + lane;

    unsigned long long a[8][2];
    #pragma unroll
    for (int b = 0; b < 8; ++b) { a[b][0] = 0ULL; a[b][1] = 0ULL; }

    const int* eb = g_edges + (size_t)node * BCAP;
    int cnt = min(g_counts[node], BCAP);
    int e = 0;
    for (; e + 7 < cnt; e += 8) {
        int p[8];
        uint2 hv[8];
        #pragma unroll
        for (int j = 0; j < 8; ++j) p[j] = eb[e + j];
        #pragma unroll
        for (int j = 0; j < 8; ++j) hv[j] = __ldcg(&xh[(size_t)(p[j] & 0xFFFFF) * 32]);
        #pragma unroll
        for (int j = 0; j < 8; ++j) {
            float2 f01 = __half22float2(*(__half2*)&hv[j].x);
            float2 f23 = __half22float2(*(__half2*)&hv[j].y);
            unsigned long long q0, q1;
            asm("mov.b64 %0, {%1, %2};" : "=l"(q0) : "f"(f01.x), "f"(f01.y));
            asm("mov.b64 %0, {%1, %2};" : "=l"(q1) : "f"(f23.x), "f"(f23.y));
            const ulonglong2* cc = (const ulonglong2*)cwp[p[j] >> 20];
            #pragma unroll
            for (int q = 0; q < 4; ++q) {
                ulonglong2 cp = cc[q];
                FFMA2(a[2*q  ][0], q0, cp.x);
                FFMA2(a[2*q  ][1], q1, cp.x);
                FFMA2(a[2*q+1][0], q0, cp.y);
                FFMA2(a[2*q+1][1], q1, cp.y);
            }
        }
    }
    for (; e < cnt; ++e) {
        int p0 = eb[e];
        uint2 hv0 = __ldcg(&xh[(size_t)(p0 & 0xFFFFF) * 32]);
        float2 f01 = __half22float2(*(__half2*)&hv0.x);
        float2 f23 = __half22float2(*(__half2*)&hv0.y);
        unsigned long long q0, q1;
        asm("mov.b64 %0, {%1, %2};" : "=l"(q0) : "f"(f01.x), "f"(f01.y));
        asm("mov.b64 %0, {%1, %2};" : "=l"(q1) : "f"(f23.x), "f"(f23.y));
        const ulonglong2* cc = (const ulonglong2*)cwp[p0 >> 20];
        #pragma unroll
        for (int q = 0; q < 4; ++q) {
            ulonglong2 cp = cc[q];
            FFMA2(a[2*q  ][0], q0, cp.x);
            FFMA2(a[2*q  ][1], q1, cp.x);
            FFMA2(a[2*q+1][0], q0, cp.y);
            FFMA2(a[2*q+1][1], q1, cp.y);
        }
    }

    #pragma unroll
    for (int b = 0; b < 8; ++b) {
        float f0, f1, f2, f3;
        asm("mov.b64 {%0, %1}, %2;" : "=f"(f0), "=f"(f1) : "l"(a[b][0]));
        asm("mov.b64 {%0, %1}, %2;" : "=f"(f2), "=f"(f3) : "l"(a[b][1]));
        __half2 h0 = __floats2half2_rn(f0, f1);
        __half2 h1 = __floats2half2_rn(f2, f3);
        arow[b * 32 + lane] = make_uint2(*(uint32_t*)&h0, *(uint32_t*)&h1);
    }
    // self-loop block (b = 8): fp32 x rounded to fp16 (exact R10)
    float4 xv = x4[(size_t)node * 32 + lane];
    __half2 h0 = __floats2half2_rn(xv.x, xv.y);
    __half2 h1 = __floats2half2_rn(xv.z, xv.w);
    arow[8 * 32 + lane] = make_uint2(*(uint32_t*)&h0, *(uint32_t*)&h1);
}

// ---------------- fp16 mma.sync GEMM (EXACT R10): out = relu(A@B^T + bias) ---
// CTA: 128(M) x 128(N), 256 threads = 8 warps (4M x 2N), warp tile 32x64.
// K streamed in 18 chunks of 64 fp16, cp.async TRIPLE buffered.
#define KC      64
#define NCH     18
#define ROWB    144
#define OFF_A   0u
#define OFF_B   18432u
#define STG     36864u
#define GEMM_SMEM (3 * STG)

__global__ void __launch_bounds__(256) k_gemm_mma(const float* __restrict__ bias,
                                                  float* __restrict__ out, int n) {
    extern __shared__ char sm[];
    __shared__ float s_bias[128];
    uint32_t sbase = smem_u32(sm);

    int tid  = threadIdx.x;
    int lane = tid & 31;
    int w    = tid >> 5;
    int mw   = w >> 1;                 // 0..3
    int nw   = w & 1;                  // 0..1
    if (tid < 128) s_bias[tid] = bias[tid];

    int m0 = blockIdx.x * 128;

    // cp.async mapping: row = tid>>1 (0..127), 4 x 16B chunks per thread
    int l_row = tid >> 1;
    int l_c0  = (tid & 1) * 4;

    // ldmatrix lane address components (b16 K-major)
    uint32_t a_lm = (uint32_t)((lane & 15) * ROWB + ((lane >> 4) << 4));
    uint32_t b_lm = (uint32_t)((((lane & 7) + ((lane >> 4) << 3)) * ROWB) + (((lane >> 3) & 1) << 4));

    float acc[2][8][4];
    #pragma unroll
    for (int i = 0; i < 2; ++i)
        #pragma unroll
        for (int nt = 0; nt < 8; ++nt)
            #pragma unroll
            for (int q = 0; q < 4; ++q) acc[i][nt][q] = 0.f;

    #define LOAD_STAGE(cidx, s) do {                                                  \
        size_t kc = (size_t)(cidx) * KC;                                              \
        uint32_t sb = sbase + (uint32_t)(s) * STG;                                     \
        _Pragma("unroll")                                                              \
        for (int j = 0; j < 4; ++j) {                                                  \
            int cc = l_c0 + j;                                                         \
            uint32_t so = (uint32_t)(l_row * ROWB + cc * 16);                          \
            cpa16(sb + OFF_A + so,                                                     \
                  (const char*)(g_ah + (size_t)(m0 + l_row) * KTOT + kc) + cc * 16);   \
            cpa16(sb + OFF_B + so,                                                     \
                  (const char*)(g_bh + (size_t)l_row * KTOT + kc) + cc * 16);          \
        }                                                                              \
        CP_COMMIT();                                                                   \
    } while (0)

    LOAD_STAGE(0, 0);
    LOAD_STAGE(1, 1);
    CP_WAIT1();
    __syncthreads();

    int stg = 0;
    for (int c = 0; c < NCH; ++c) {
        if (c + 2 < NCH) {
            int ns = stg + 2; if (ns >= 3) ns -= 3;
            LOAD_STAGE(c + 2, ns);
        }

        uint32_t sb = sbase + (uint32_t)stg * STG;
        #pragma unroll
        for (int ks = 0; ks < 4; ++ks) {           // 4 x k16 slices (32B each)
            uint32_t kb = ks * 32;
            uint32_t A[2][4];
            #pragma unroll
            for (int i = 0; i < 2; ++i)
                ldsm4(A[i], sb + OFF_A + (uint32_t)((mw * 32 + i * 16) * ROWB) + a_lm + kb);
            #pragma unroll
            for (int jp = 0; jp < 4; ++jp) {
                uint32_t B[4];
                ldsm4(B, sb + OFF_B + (uint32_t)((nw * 64 + jp * 16) * ROWB) + b_lm + kb);
                #pragma unroll
                for (int i = 0; i < 2; ++i) {
                    mma16816(acc[i][2*jp  ], A[i], B[0], B[1]);
                    mma16816(acc[i][2*jp+1], A[i], B[2], B[3]);
                }
            }
        }

        if (c + 1 < NCH) {
            if (c + 2 < NCH) { CP_WAIT1(); } else { CP_WAIT0(); }
            __syncthreads();
        }
        if (++stg >= 3) stg = 0;
    }

    // ---- epilogue: bias + relu ----
    #pragma unroll
    for (int i = 0; i < 2; ++i) {
        int mbase = m0 + mw * 32 + i * 16 + (lane >> 2);
        #pragma unroll
        for (int nt = 0; nt < 8; ++nt) {
            int col = nw * 64 + nt * 8 + 2 * (lane & 3);
            float b0 = s_bias[col], b1 = s_bias[col + 1];
            float* cfr = acc[i][nt];
            if (mbase < n) {
                float2 v = make_float2(fmaxf(cfr[0] + b0, 0.f), fmaxf(cfr[1] + b1, 0.f));
                *(float2*)(out + (size_t)mbase * DOUTC + col) = v;
            }
            if (mbase + 8 < n) {
                float2 v = make_float2(fmaxf(cfr[2] + b0, 0.f), fmaxf(cfr[3] + b1, 0.f));
                *(float2*)(out + (size_t)(mbase + 8) * DOUTC + col) = v;
            }
        }
    }
}

// ---------------- launch ----------------
extern "C" void kernel_launch(void* const* d_in, const int* in_sizes, int n_in,
                              void* d_out, int out_size) {
    const float* x      = (const float*)d_in[0];
    const int*   src    = (const int*)  d_in[1];
    const int*   dst    = (const int*)  d_in[2];
    const int*   etypes = (const int*)  d_in[3];
    const float* weight = (const float*)d_in[4];
    const float* w_comp = (const float*)d_in[5];
    const float* h_bias = (const float*)d_in[6];
    const float* loop_w = (const float*)d_in[7];
    float* out = (float*)d_out;

    int n = in_sizes[0] / DINC;   // 50000
    int e = in_sizes[1];          // 1600000

    static int attr_set = 0;
    if (!attr_set) {
        cudaFuncSetAttribute(k_gemm_mma, cudaFuncAttributeMaxDynamicSharedMemorySize, GEMM_SMEM);
        attr_set = 1;
    }

    int nfront = n * (DINC / 4);  // 1.6M threads covers all front-end work
    k_zero  <<<(n + 256) / 256, 256>>>(n);
    k_front <<<(nfront + 255) / 256, 256>>>((const float4*)x, weight, loop_w,
                                            src, dst, etypes, e, n);
    k_aggregate<<<MPAD / 8, 256>>>((const float4*)x, w_comp, n);
    k_gemm_mma<<<MPAD / 128, 256, GEMM_SMEM>>>(h_bias, out, n);
}